// round 12
// baseline (speedup 1.0000x reference)
#include <cuda_runtime.h>
#include <cuda_bf16.h>
#include <math.h>

// Problem: b=2, f=8, c=64, h=w=256  (fp32)
//   k_sum[bf,c] = sum_{hw} nbr[bf,c,hw]
//   out[bf,hw]  = sigmoid( sum_c ref[bf,c,hw] * k_sum[bf,c] )
// HBM streaming: 2 x 268MB reads + 4MB write.
// R11 had an indexing bug (grid 256 but >>5 decode). Fixed here:
// 256 blocks x 512 threads x one v8/channel (16 blocks per bf).

#define BF     16          // b*f
#define C      64
#define HW     65536       // 256*256
#define HW8    8192        // HW / 8

// 256-bit streaming load: 8 floats, 32B-aligned (Blackwell LDG.E.256).
__device__ __forceinline__ void ldcs_v8(const float* __restrict__ p,
                                        float& a, float& b, float& c, float& d,
                                        float& e, float& f, float& g, float& h) {
    asm volatile("ld.global.cs.v8.f32 {%0,%1,%2,%3,%4,%5,%6,%7}, [%8];"
                 : "=f"(a), "=f"(b), "=f"(c), "=f"(d),
                   "=f"(e), "=f"(f), "=f"(g), "=f"(h)
                 : "l"(p));
}

__device__ float g_ksum[BF * C];

// ---------------------------------------------------------------------------
// Kernel 1: per-channel-plane reduction. One block per (bf,c) plane (256 KB
// contiguous). 256 threads * 32 v8 loads each.
// ---------------------------------------------------------------------------
__global__ __launch_bounds__(256) void ksum_kernel(const float* __restrict__ nbr) {
    const int ch = blockIdx.x;                       // 0..1023 == bf*64 + c
    const float* __restrict__ p = nbr + (size_t)ch * HW;

    float s = 0.0f;
    #pragma unroll 4
    for (int i = threadIdx.x; i < HW8; i += 256) {
        float a, b, c, d, e, f, g, h;
        ldcs_v8(p + (size_t)i * 8, a, b, c, d, e, f, g, h);
        s += ((a + b) + (c + d)) + ((e + f) + (g + h));
    }

    #pragma unroll
    for (int off = 16; off > 0; off >>= 1)
        s += __shfl_xor_sync(0xffffffffu, s, off);

    __shared__ float warp_sums[8];
    const int lane = threadIdx.x & 31;
    const int wid  = threadIdx.x >> 5;
    if (lane == 0) warp_sums[wid] = s;
    __syncthreads();

    if (wid == 0) {
        float t = (lane < 8) ? warp_sums[lane] : 0.0f;
        #pragma unroll
        for (int off = 4; off > 0; off >>= 1)
            t += __shfl_xor_sync(0xffffffffu, t, off);
        if (lane == 0) g_ksum[ch] = t;
    }
}

// ---------------------------------------------------------------------------
// Kernel 2: weighted channel contraction + sigmoid.
// 256 blocks x 512 threads, ONE v8 (32B) load per thread per channel.
// 16 blocks per bf, 16 KB contiguous window per channel step.
// ---------------------------------------------------------------------------
__global__ __launch_bounds__(512) void weight_kernel(const float* __restrict__ ref,
                                                     float* __restrict__ out) {
    const int bf  = blockIdx.x >> 4;                     // 16 blocks per bf
    const int win = (blockIdx.x & 15) << 12;             // window base (floats)
    const int p   = win + threadIdx.x * 8;               // float index in plane

    __shared__ float sk[C];
    if (threadIdx.x < C) sk[threadIdx.x] = g_ksum[bf * C + threadIdx.x];
    __syncthreads();

    const float* __restrict__ base = ref + (size_t)bf * C * HW + p;

    float a0 = 0.f, a1 = 0.f, a2 = 0.f, a3 = 0.f;
    float a4 = 0.f, a5 = 0.f, a6 = 0.f, a7 = 0.f;

    #pragma unroll
    for (int c = 0; c < C; c++) {
        float v0, v1, v2, v3, v4, v5, v6, v7;
        ldcs_v8(base + (size_t)c * HW, v0, v1, v2, v3, v4, v5, v6, v7);
        const float k = sk[c];
        a0 = fmaf(v0, k, a0);
        a1 = fmaf(v1, k, a1);
        a2 = fmaf(v2, k, a2);
        a3 = fmaf(v3, k, a3);
        a4 = fmaf(v4, k, a4);
        a5 = fmaf(v5, k, a5);
        a6 = fmaf(v6, k, a6);
        a7 = fmaf(v7, k, a7);
    }

    float4 r0, r1;
    r0.x = __fdividef(1.0f, 1.0f + __expf(-a0));
    r0.y = __fdividef(1.0f, 1.0f + __expf(-a1));
    r0.z = __fdividef(1.0f, 1.0f + __expf(-a2));
    r0.w = __fdividef(1.0f, 1.0f + __expf(-a3));
    r1.x = __fdividef(1.0f, 1.0f + __expf(-a4));
    r1.y = __fdividef(1.0f, 1.0f + __expf(-a5));
    r1.z = __fdividef(1.0f, 1.0f + __expf(-a6));
    r1.w = __fdividef(1.0f, 1.0f + __expf(-a7));

    float4* o = reinterpret_cast<float4*>(out + (size_t)bf * HW + p);
    __stcs(o,     r0);
    __stcs(o + 1, r1);
}

// ---------------------------------------------------------------------------
extern "C" void kernel_launch(void* const* d_in, const int* in_sizes, int n_in,
                              void* d_out, int out_size) {
    const float* nbr = (const float*)d_in[0];
    const float* ref = (const float*)d_in[1];
    float* out = (float*)d_out;

    ksum_kernel<<<BF * C, 256>>>(nbr);
    weight_kernel<<<BF * 16, 512>>>(ref, out);
}

// round 13
// speedup vs baseline: 1.0144x; 1.0144x over previous
#include <cuda_runtime.h>
#include <cuda_bf16.h>
#include <math.h>

// SpatialWeight — FINAL (R10 config, best measured).
// Problem: b=2, f=8, c=64, h=w=256  (fp32)
//   k_sum[bf,c] = sum_{hw} nbr[bf,c,hw]
//   out[bf,hw]  = sigmoid( sum_c ref[bf,c,hw] * k_sum[bf,c] )
// HBM streaming: 2 x 268MB reads + 4MB write.
// Measured: ksum ~39-41us @6.7-6.9TB/s; weight 42.5us @6.40TB/s (plateau
// confirmed across window size / warps / request width / load mechanism).

#define BF     16          // b*f
#define C      64
#define HW     65536       // 256*256
#define HW8    8192        // HW / 8

// 256-bit streaming load: 8 floats, 32B-aligned (Blackwell LDG.E.256).
__device__ __forceinline__ void ldcs_v8(const float* __restrict__ p,
                                        float& a, float& b, float& c, float& d,
                                        float& e, float& f, float& g, float& h) {
    asm volatile("ld.global.cs.v8.f32 {%0,%1,%2,%3,%4,%5,%6,%7}, [%8];"
                 : "=f"(a), "=f"(b), "=f"(c), "=f"(d),
                   "=f"(e), "=f"(f), "=f"(g), "=f"(h)
                 : "l"(p));
}

__device__ float g_ksum[BF * C];

// ---------------------------------------------------------------------------
// Kernel 1: per-channel-plane reduction. One block per (bf,c) plane (256 KB
// contiguous). 256 threads * 32 v8 streaming loads each.
// ---------------------------------------------------------------------------
__global__ __launch_bounds__(256) void ksum_kernel(const float* __restrict__ nbr) {
    const int ch = blockIdx.x;                       // 0..1023 == bf*64 + c
    const float* __restrict__ p = nbr + (size_t)ch * HW;

    float s = 0.0f;
    #pragma unroll 4
    for (int i = threadIdx.x; i < HW8; i += 256) {
        float a, b, c, d, e, f, g, h;
        ldcs_v8(p + (size_t)i * 8, a, b, c, d, e, f, g, h);
        s += ((a + b) + (c + d)) + ((e + f) + (g + h));
    }

    #pragma unroll
    for (int off = 16; off > 0; off >>= 1)
        s += __shfl_xor_sync(0xffffffffu, s, off);

    __shared__ float warp_sums[8];
    const int lane = threadIdx.x & 31;
    const int wid  = threadIdx.x >> 5;
    if (lane == 0) warp_sums[wid] = s;
    __syncthreads();

    if (wid == 0) {
        float t = (lane < 8) ? warp_sums[lane] : 0.0f;
        #pragma unroll
        for (int off = 4; off > 0; off >>= 1)
            t += __shfl_xor_sync(0xffffffffu, t, off);
        if (lane == 0) g_ksum[ch] = t;
    }
}

// ---------------------------------------------------------------------------
// Kernel 2: weighted channel contraction + sigmoid.
// 512 blocks x 256 threads, ONE v8 (32B) streaming load per thread per
// channel -> 8 KB contiguous window per channel step (measured optimum).
// __stcs streaming stores, fast-math sigmoid.
// ---------------------------------------------------------------------------
__global__ __launch_bounds__(256) void weight_kernel(const float* __restrict__ ref,
                                                     float* __restrict__ out) {
    const int bf  = blockIdx.x >> 5;                     // 32 blocks per bf
    const int win = (blockIdx.x & 31) << 11;             // window base (floats)
    const int p   = win + threadIdx.x * 8;               // float index in plane

    __shared__ float sk[C];
    if (threadIdx.x < C) sk[threadIdx.x] = g_ksum[bf * C + threadIdx.x];
    __syncthreads();

    const float* __restrict__ base = ref + (size_t)bf * C * HW + p;

    float a0 = 0.f, a1 = 0.f, a2 = 0.f, a3 = 0.f;
    float a4 = 0.f, a5 = 0.f, a6 = 0.f, a7 = 0.f;

    #pragma unroll
    for (int c = 0; c < C; c++) {
        float v0, v1, v2, v3, v4, v5, v6, v7;
        ldcs_v8(base + (size_t)c * HW, v0, v1, v2, v3, v4, v5, v6, v7);
        const float k = sk[c];
        a0 = fmaf(v0, k, a0);
        a1 = fmaf(v1, k, a1);
        a2 = fmaf(v2, k, a2);
        a3 = fmaf(v3, k, a3);
        a4 = fmaf(v4, k, a4);
        a5 = fmaf(v5, k, a5);
        a6 = fmaf(v6, k, a6);
        a7 = fmaf(v7, k, a7);
    }

    float4 r0, r1;
    r0.x = __fdividef(1.0f, 1.0f + __expf(-a0));
    r0.y = __fdividef(1.0f, 1.0f + __expf(-a1));
    r0.z = __fdividef(1.0f, 1.0f + __expf(-a2));
    r0.w = __fdividef(1.0f, 1.0f + __expf(-a3));
    r1.x = __fdividef(1.0f, 1.0f + __expf(-a4));
    r1.y = __fdividef(1.0f, 1.0f + __expf(-a5));
    r1.z = __fdividef(1.0f, 1.0f + __expf(-a6));
    r1.w = __fdividef(1.0f, 1.0f + __expf(-a7));

    float4* o = reinterpret_cast<float4*>(out + (size_t)bf * HW + p);
    __stcs(o,     r0);
    __stcs(o + 1, r1);
}

// ---------------------------------------------------------------------------
extern "C" void kernel_launch(void* const* d_in, const int* in_sizes, int n_in,
                              void* d_out, int out_size) {
    const float* nbr = (const float*)d_in[0];
    const float* ref = (const float*)d_in[1];
    float* out = (float*)d_out;

    ksum_kernel<<<BF * C, 256>>>(nbr);
    weight_kernel<<<BF * HW / 2048, 256>>>(ref, out);
}